// round 14
// baseline (speedup 1.0000x reference)
#include <cuda_runtime.h>
#include <cuda_fp16.h>
#include <cstdint>

#define B_TOT 8192
#define NSM   148

// ---------------- device scratch ----------------
__device__ __align__(16) __half g_W2f[256 * 256];   // W2 f16, k(i)-row-major
__device__ __align__(16) __half g_W3T[256 * 64];    // W3^T f16: [i][o]
__device__ __align__(16) float  g_P[256 * 256];     // P = W1 W1^T (f32)
__device__ __align__(16) float  g_f[B_TOT * 64];
__device__ unsigned g_r1[B_TOT * 8];
__device__ unsigned g_r2[B_TOT * 8];

// ---------------- helpers ----------------
__device__ __forceinline__ uint32_t smem_u32(const void* p) {
    uint32_t a;
    asm("{ .reg .u64 t; cvta.to.shared.u64 t, %1; cvt.u32.u64 %0, t; }" : "=r"(a) : "l"(p));
    return a;
}
__device__ __forceinline__ void cp16(uint32_t dst, const void* src) {
    asm volatile("cp.async.cg.shared.global [%0], [%1], 16;" :: "r"(dst), "l"(src) : "memory");
}
#define CP_COMMIT() asm volatile("cp.async.commit_group;" ::: "memory")
#define CP_WAIT0()  asm volatile("cp.async.wait_group 0;" ::: "memory")
__device__ __forceinline__ void ldm4t(uint32_t& r0, uint32_t& r1, uint32_t& r2, uint32_t& r3,
                                      uint32_t addr) {
    asm volatile("ldmatrix.sync.aligned.m8n8.x4.trans.shared.b16 {%0,%1,%2,%3}, [%4];"
                 : "=r"(r0), "=r"(r1), "=r"(r2), "=r"(r3) : "r"(addr));
}
__device__ __forceinline__ void mma16816(float c[4], uint32_t a0, uint32_t a1,
                                         uint32_t a2, uint32_t a3,
                                         uint32_t b0, uint32_t b1) {
    asm volatile(
        "mma.sync.aligned.m16n8k16.row.col.f32.f16.f16.f32 "
        "{%0,%1,%2,%3}, {%4,%5,%6,%7}, {%8,%9}, {%0,%1,%2,%3};"
        : "+f"(c[0]), "+f"(c[1]), "+f"(c[2]), "+f"(c[3])
        : "r"(a0), "r"(a1), "r"(a2), "r"(a3), "r"(b0), "r"(b1));
}

// bucketed ordering for mask2 (keeps gathered W2/W3T LDSM rows residue-spread)
__device__ __forceinline__ int bucket_rank(const unsigned* m, int j) {
    const int wj = j >> 5, b = j & 31, r = j & 7;
    const unsigned res = 0x01010101u << r;
    const unsigned below = (b == 0) ? 0u : ((1u << b) - 1u);
    int rank = 0;
    #pragma unroll
    for (int w = 0; w < 8; ++w)
        if (w < wj) rank += __popc(m[w] & res);
    rank += __popc(m[wj] & res & below);
    return rank;
}
__device__ __forceinline__ int bucket_pos(const unsigned* c, int rank, int r) {
    int pos = 0;
    #pragma unroll
    for (int r2 = 0; r2 < 8; ++r2) {
        int cc = (int)c[r2];
        pos += (rank < cc) ? rank : cc;
        if (r2 < r && cc > rank) pos += 1;
    }
    return pos;
}
__device__ __forceinline__ unsigned res_count(const unsigned* m, int r) {
    const unsigned res = 0x01010101u << r;
    unsigned c = 0;
    #pragma unroll
    for (int w = 0; w < 8; ++w) c += __popc(m[w] & res);
    return c;
}

// =====================================================================
// prep: f16 copies
// =====================================================================
__global__ void prep_kernel(const float* __restrict__ W2, const float* __restrict__ W3) {
    int idx = blockIdx.x * 256 + threadIdx.x;
    if (idx < 65536) g_W2f[idx] = __float2half_rn(W2[idx]);
    else {
        int l = idx - 65536;           // < 16384
        int i = l >> 6, o = l & 63;
        g_W3T[l] = __float2half_rn(W3[o * 256 + i]);
    }
}

// prepP: P = W1 W1^T  (grid 256, block 256)
__global__ void prepP_kernel(const float* __restrict__ W1) {
    __shared__ float row[256];
    const int r = blockIdx.x, c = threadIdx.x;
    row[c] = W1[r * 256 + c];
    __syncthreads();
    float s = 0.f;
    const float4* wc = (const float4*)(W1 + c * 256);
    for (int d = 0; d < 64; ++d) {
        float4 w = __ldg(wc + d);
        s = fmaf(w.x, row[d * 4 + 0], s);
        s = fmaf(w.y, row[d * 4 + 1], s);
        s = fmaf(w.z, row[d * 4 + 2], s);
        s = fmaf(w.w, row[d * 4 + 3], s);
    }
    g_P[r * 256 + c] = s;
}

// =====================================================================
// forward MLP (fp32 exact) + ReLU bitmasks, 16 samples / block
// =====================================================================
__global__ __launch_bounds__(256) void fwd_kernel(
    const float* __restrict__ X,
    const float* __restrict__ W1, const float* __restrict__ B1,
    const float* __restrict__ W2, const float* __restrict__ B2,
    const float* __restrict__ W3, const float* __restrict__ B3)
{
    __shared__ float bufA[16][256];
    __shared__ float bufB[16][256];
    const int t = threadIdx.x, lane = t & 31, wid = t >> 5;
    const int s0 = blockIdx.x * 16;

    {
        const float4* src = (const float4*)(X + (size_t)s0 * 256);
        float4* dst = (float4*)&bufA[0][0];
        for (int i = t; i < 16 * 64; i += 256) dst[i] = __ldg(src + i);
    }
    __syncthreads();

    float acc[16];
    {   // layer 1
        #pragma unroll
        for (int s = 0; s < 16; ++s) acc[s] = 0.f;
        const float4* wr = (const float4*)(W1 + t * 256);
        for (int j = 0; j < 64; ++j) {
            float4 w = __ldg(wr + j);
            #pragma unroll
            for (int s = 0; s < 16; ++s) {
                float4 xv = ((const float4*)bufA[s])[j];
                acc[s] = fmaf(w.x, xv.x, acc[s]); acc[s] = fmaf(w.y, xv.y, acc[s]);
                acc[s] = fmaf(w.z, xv.z, acc[s]); acc[s] = fmaf(w.w, xv.w, acc[s]);
            }
        }
        const float b = __ldg(B1 + t);
        #pragma unroll
        for (int s = 0; s < 16; ++s) {
            float z = acc[s] + b;
            unsigned m = __ballot_sync(0xffffffffu, z > 0.f);
            if (lane == 0) g_r1[(size_t)(s0 + s) * 8 + wid] = m;
            bufB[s][t] = z > 0.f ? z : 0.f;
        }
    }
    __syncthreads();
    {   // layer 2
        #pragma unroll
        for (int s = 0; s < 16; ++s) acc[s] = 0.f;
        const float4* wr = (const float4*)(W2 + t * 256);
        for (int j = 0; j < 64; ++j) {
            float4 w = __ldg(wr + j);
            #pragma unroll
            for (int s = 0; s < 16; ++s) {
                float4 xv = ((const float4*)bufB[s])[j];
                acc[s] = fmaf(w.x, xv.x, acc[s]); acc[s] = fmaf(w.y, xv.y, acc[s]);
                acc[s] = fmaf(w.z, xv.z, acc[s]); acc[s] = fmaf(w.w, xv.w, acc[s]);
            }
        }
        const float b = __ldg(B2 + t);
        #pragma unroll
        for (int s = 0; s < 16; ++s) {
            float z = acc[s] + b;
            unsigned m = __ballot_sync(0xffffffffu, z > 0.f);
            if (lane == 0) g_r2[(size_t)(s0 + s) * 8 + wid] = m;
            bufA[s][t] = z > 0.f ? z : 0.f;
        }
    }
    __syncthreads();
    {   // layer 3
        const int o = t & 63, sg = t >> 6;
        float a4[4] = {0.f, 0.f, 0.f, 0.f};
        const float4* wr = (const float4*)(W3 + o * 256);
        for (int j = 0; j < 64; ++j) {
            float4 w = __ldg(wr + j);
            #pragma unroll
            for (int q = 0; q < 4; ++q) {
                float4 hv = ((const float4*)bufA[sg * 4 + q])[j];
                a4[q] = fmaf(w.x, hv.x, a4[q]); a4[q] = fmaf(w.y, hv.y, a4[q]);
                a4[q] = fmaf(w.z, hv.z, a4[q]); a4[q] = fmaf(w.w, hv.w, a4[q]);
            }
        }
        const float b = __ldg(B3 + o);
        #pragma unroll
        for (int q = 0; q < 4; ++q)
            g_f[(size_t)(s0 + sg * 4 + q) * 64 + o] = a4[q] + b;
    }
}

// =====================================================================
// Fused jac kernel: persistent, 512 thr.
// Resident: W2 (264x528), W3T (264x144). Ustage (64 x 528, o-major,
// col-compacted active j). GEMM1: U = gathered-W3T^T @ gathered-W2.
// GEMM2: Q = U^T U (K=o=64, contiguous rows). ss = sum Q .* gathered P.
// =====================================================================
#define J_W2   0u
#define J_W3T  139392u
#define J_UST  177408u
#define J_MSC  211200u
#define SMEMJ  213600

__global__ __launch_bounds__(512, 1) void jac_kernel(const float* __restrict__ Kp,
                                                     float* __restrict__ out) {
    extern __shared__ char smem[];
    const uint32_t sb = smem_u32(smem);
    const int tid = threadIdx.x, lane = tid & 31, wid = tid >> 5;
    const int g = lane >> 2, tig = lane & 3;
    const int wm = wid & 1, wn = wid >> 1;      // GEMM1: 2 x 8, 32x32 tiles
    const int qwm = wid & 3, qwn = wid >> 2;    // GEMM2: 4 x 4, 32x32 tiles

    unsigned* mbuf = (unsigned*)(smem + J_MSC);             // 2 x 16 words
    float*    fbuf = (float*)(smem + J_MSC + 128);          // 2 x 64
    unsigned* m2s  = (unsigned*)(smem + J_MSC + 640);       // 8
    unsigned* m1s  = (unsigned*)(smem + J_MSC + 672);       // 8
    unsigned* c2s  = (unsigned*)(smem + J_MSC + 704);       // 8
    unsigned* p1s  = (unsigned*)(smem + J_MSC + 736);       // 9 (+pad)
    unsigned short* pos1 = (unsigned short*)(smem + J_MSC + 784);   // 256
    unsigned short* idx1 = (unsigned short*)(smem + J_MSC + 1296);  // 256
    unsigned short* idx2 = (unsigned short*)(smem + J_MSC + 1808);  // 256
    float*    red  = (float*)(smem + J_MSC + 2320);         // 16

    // ---- resident loads ----
    for (int c = tid; c < 8192; c += 512)
        cp16(sb + J_W2 + (uint32_t)(c >> 5) * 528u + (uint32_t)(c & 31) * 16u,
             (const char*)g_W2f + (size_t)c * 16);
    for (int c = tid; c < 2048; c += 512)
        cp16(sb + J_W3T + (uint32_t)(c >> 3) * 144u + (uint32_t)(c & 7) * 16u,
             (const char*)g_W3T + (size_t)c * 16);
    if (tid < 264) {                    // zero pad rows 256..263 of W2
        int r = tid / 33, sg = tid % 33;
        *(uint4*)(smem + J_W2 + (uint32_t)(256 + r) * 528u + (uint32_t)sg * 16u) =
            make_uint4(0, 0, 0, 0);
    } else if (tid < 336) {             // zero pad rows 256..263 of W3T
        int l = tid - 264, r = l / 9, sg = l % 9;
        *(uint4*)(smem + J_W3T + (uint32_t)(256 + r) * 144u + (uint32_t)sg * 16u) =
            make_uint4(0, 0, 0, 0);
    }
    const int s0 = blockIdx.x;
    if (tid < 2)       cp16(sb + J_MSC + tid * 16u, (const char*)(g_r2 + (size_t)s0 * 8) + tid * 16);
    else if (tid < 4)  cp16(sb + J_MSC + 32u + (tid - 2) * 16u,
                            (const char*)(g_r1 + (size_t)s0 * 8) + (tid - 2) * 16);
    else if (tid < 20) cp16(sb + J_MSC + 128u + (tid - 4) * 16u,
                            (const char*)(g_f + (size_t)s0 * 64) + (tid - 4) * 16);
    CP_COMMIT();

    const float kk = __ldg(Kp);
    const float sp = (kk > 20.f) ? kk : log1pf(expf(kk));

    // lane constants (trans-LDSM pattern, shared by both GEMMs)
    const int rlA = (lane & 7) + ((lane >> 4) & 1) * 8;
    const int rlB = (lane & 7) + ((lane >> 3) & 1) * 8;
    const uint32_t aColT = ((lane >> 3) & 1) * 16;
    const uint32_t bColT = ((lane >> 4) & 1) * 16;

    int it = 0;
    for (int s = s0; s < B_TOT; s += NSM, ++it) {
        const int pb = it & 1;
        CP_WAIT0();
        __syncthreads();
        if (tid < 8)       m2s[tid]     = mbuf[pb * 16 + tid];
        else if (tid < 16) m1s[tid - 8] = mbuf[pb * 16 + tid];
        __syncthreads();
        {   // prefetch next sample masks + f
            const int sn = s + NSM;
            if (sn < B_TOT) {
                const uint32_t mb = sb + J_MSC + (uint32_t)(pb ^ 1) * 64u;
                const uint32_t fb = sb + J_MSC + 128u + (uint32_t)(pb ^ 1) * 256u;
                if (tid < 2)       cp16(mb + tid * 16u, (const char*)(g_r2 + (size_t)sn * 8) + tid * 16);
                else if (tid < 4)  cp16(mb + 32u + (tid - 2) * 16u,
                                        (const char*)(g_r1 + (size_t)sn * 8) + (tid - 2) * 16);
                else if (tid < 20) cp16(fb + (tid - 4) * 16u,
                                        (const char*)(g_f + (size_t)sn * 64) + (tid - 4) * 16);
            }
            CP_COMMIT();
        }
        if (tid < 8) c2s[tid] = res_count(m2s, tid);
        if (tid == 32) {
            unsigned p = 0;
            #pragma unroll
            for (int w = 0; w < 8; ++w) { p1s[w] = p; p += __popc(m1s[w]); }
            p1s[8] = p;
        }
        __syncthreads();
        int n2 = 0;
        #pragma unroll
        for (int r = 0; r < 8; ++r) n2 += (int)c2s[r];
        const int n1 = p1s[8];
        int nk2 = (n2 + 15) >> 4; if (nk2 < 1) nk2 = 1;
        const int nk1 = (n1 + 15) >> 4;
        if (tid < 256) {
            const int j = tid;
            if ((m2s[j >> 5] >> (j & 31)) & 1u) {
                int rank = bucket_rank(m2s, j);
                idx2[bucket_pos(c2s, rank, j & 7)] = (unsigned short)j;
            }
            if (tid >= n2) idx2[tid] = (unsigned short)(256 + (tid & 7));
            if ((m1s[j >> 5] >> (j & 31)) & 1u) {
                const int b = j & 31;
                const unsigned below = (b == 0) ? 0u : ((1u << b) - 1u);
                unsigned p = p1s[j >> 5] + __popc(m1s[j >> 5] & below);
                pos1[j] = (unsigned short)p;
                idx1[p] = (unsigned short)j;
            }
        }
        __syncthreads();

        // ---- GEMM1: U[o=64][j=256] over K = n2 (gathered rows) ----
        float acc[2][4][4];
        #pragma unroll
        for (int mt = 0; mt < 2; ++mt)
            #pragma unroll
            for (int nt = 0; nt < 4; ++nt)
                #pragma unroll
                for (int q = 0; q < 4; ++q) acc[mt][nt][q] = 0.f;

        for (int kt = 0; kt < nk2; ++kt) {
            const uint32_t rA = idx2[kt * 16 + rlA];
            const uint32_t rB = idx2[kt * 16 + rlB];
            const uint32_t aadr = sb + J_W3T + rA * 144u + aColT + (uint32_t)wm * 64u;
            const uint32_t badr = sb + J_W2 + rB * 528u + bColT + (uint32_t)wn * 64u;
            uint32_t a[2][4], b[2][4];
            #pragma unroll
            for (int mt = 0; mt < 2; ++mt)
                ldm4t(a[mt][0], a[mt][1], a[mt][2], a[mt][3], aadr + (uint32_t)mt * 32u);
            #pragma unroll
            for (int ng = 0; ng < 2; ++ng)
                ldm4t(b[ng][0], b[ng][1], b[ng][2], b[ng][3], badr + (uint32_t)ng * 32u);
            #pragma unroll
            for (int mt = 0; mt < 2; ++mt)
                #pragma unroll
                for (int nt = 0; nt < 4; ++nt)
                    mma16816(acc[mt][nt], a[mt][0], a[mt][1], a[mt][2], a[mt][3],
                             b[nt >> 1][(nt & 1) * 2], b[nt >> 1][(nt & 1) * 2 + 1]);
        }

        // ---- scatter U into Ustage: row m(=o) pitch 528, col = pos1[j] (compacted) ----
        #pragma unroll
        for (int nt = 0; nt < 4; ++nt)
            #pragma unroll
            for (int ql = 0; ql < 2; ++ql) {
                const int j = wn * 32 + nt * 8 + 2 * tig + ql;
                if ((m1s[j >> 5] >> (j & 31)) & 1u) {
                    const uint32_t pp = pos1[j];
                    #pragma unroll
                    for (int mt = 0; mt < 2; ++mt)
                        #pragma unroll
                        for (int qh = 0; qh < 2; ++qh) {
                            const int m = wm * 32 + mt * 16 + g + qh * 8;
                            *(__half*)(smem + J_UST + (uint32_t)m * 528u + pp * 2u) =
                                __float2half_rn(acc[mt][nt][qh * 2 + ql]);
                        }
                }
            }
        __syncthreads();

        // ---- GEMM2: Q = U^T U (K = o = 64, contiguous rows), weighted by P ----
        float ss = 0.f;
        if (n1 > 0) {
            const int nQ = nk1 * 16;
            const int nquad = (nQ > 128) ? 2 : 1;
            for (int qm = 0; qm < nquad; ++qm)
                for (int qn = qm; qn < nquad; ++qn) {
                    const int QM = qm * 128 + qwm * 32;
                    const int QN = qn * 128 + qwn * 32;
                    if (QM >= nQ || QN >= nQ) continue;
                    if (qm == qn && qwn < qwm) continue;
                    const float wf = (qn > qm) ? 2.f : ((qwn > qwm) ? 2.f : 1.f);
                    float qa[2][4][4];
                    #pragma unroll
                    for (int mt = 0; mt < 2; ++mt)
                        #pragma unroll
                        for (int nt = 0; nt < 4; ++nt)
                            #pragma unroll
                            for (int q = 0; q < 4; ++q) qa[mt][nt][q] = 0.f;
                    #pragma unroll
                    for (int kt = 0; kt < 4; ++kt) {
                        const uint32_t aadr = sb + J_UST + (uint32_t)(kt * 16 + rlA) * 528u
                                              + (uint32_t)QM * 2u + aColT;
                        const uint32_t badr = sb + J_UST + (uint32_t)(kt * 16 + rlB) * 528u
                                              + (uint32_t)QN * 2u + bColT;
                        uint32_t a[2][4], b[2][4];
                        #pragma unroll
                        for (int mt = 0; mt < 2; ++mt)
                            ldm4t(a[mt][0], a[mt][1], a[mt][2], a[mt][3], aadr + (uint32_t)mt * 32u);
                        #pragma unroll
                        for (int ng = 0; ng < 2; ++ng)
                            ldm4t(b[ng][0], b[ng][1], b[ng][2], b[ng][3], badr + (uint32_t)ng * 32u);
                        #pragma unroll
                        for (int mt = 0; mt < 2; ++mt)
                            #pragma unroll
                            for (int nt = 0; nt < 4; ++nt)
                                mma16816(qa[mt][nt], a[mt][0], a[mt][1], a[mt][2], a[mt][3],
                                         b[nt >> 1][(nt & 1) * 2], b[nt >> 1][(nt & 1) * 2 + 1]);
                    }
                    // weight by gathered P
                    #pragma unroll
                    for (int nt = 0; nt < 4; ++nt)
                        #pragma unroll
                        for (int ql = 0; ql < 2; ++ql) {
                            const int jc = QN + nt * 8 + 2 * tig + ql;
                            if (jc < n1) {
                                const int j2 = idx1[jc];
                                #pragma unroll
                                for (int mt = 0; mt < 2; ++mt)
                                    #pragma unroll
                                    for (int qh = 0; qh < 2; ++qh) {
                                        const int jr = QM + mt * 16 + g + qh * 8;
                                        if (jr < n1) {
                                            const float pv = __ldg(&g_P[(size_t)idx1[jr] * 256 + j2]);
                                            ss = fmaf(qa[mt][nt][qh * 2 + ql] * wf, pv, ss);
                                        }
                                    }
                            }
                        }
                }
        }

        // ---- reduce ss + epilogue ----
        #pragma unroll
        for (int off = 16; off; off >>= 1)
            ss += __shfl_xor_sync(0xffffffffu, ss, off);
        if (lane == 0) red[wid] = ss;
        __syncthreads();
        if (tid < 64) {
            float jn2 = 0.f;
            #pragma unroll
            for (int w = 0; w < 16; ++w) jn2 += red[w];
            const float fv = fbuf[pb * 64 + tid];
            out[(size_t)s * 64 + tid] = tanhf(sp * fv / (sqrtf(jn2) + 1e-4f));
        }
        __syncthreads();
    }
}

// =====================================================================
extern "C" void kernel_launch(void* const* d_in, const int* in_sizes, int n_in,
                              void* d_out, int out_size)
{
    const float* X  = (const float*)d_in[0];
    const float* W1 = (const float*)d_in[1];
    const float* B1 = (const float*)d_in[2];
    const float* W2 = (const float*)d_in[3];
    const float* B2 = (const float*)d_in[4];
    const float* W3 = (const float*)d_in[5];
    const float* B3 = (const float*)d_in[6];
    const float* Kp = (const float*)d_in[7];
    float* out = (float*)d_out;

    cudaFuncSetAttribute(jac_kernel, cudaFuncAttributeMaxDynamicSharedMemorySize, SMEMJ);

    prep_kernel<<<320, 256>>>(W2, W3);
    prepP_kernel<<<256, 256>>>(W1);
    fwd_kernel<<<B_TOT / 16, 256>>>(X, W1, B1, W2, B2, W3, B3);
    jac_kernel<<<NSM, 512, SMEMJ>>>(Kp, out);
}

// round 16
// speedup vs baseline: 1.3286x; 1.3286x over previous
#include <cuda_runtime.h>
#include <cuda_fp16.h>
#include <cstdint>

#define B_TOT 8192

// ---------------- device scratch ----------------
__device__ __align__(16) __half g_W2f[256 * 256];  // W2 f16 (B of GEMM1, k-row-major)
__device__ __align__(16) __half g_W1f[256 * 256];  // W1 f16 (B of GEMM2)
__device__ __align__(16) __half g_W3T[256 * 64];   // W3^T f16 (A of GEMM1: [i][o])
__device__ __align__(16) float  g_f[B_TOT * 64];
__device__ unsigned g_r1[B_TOT * 8];
__device__ unsigned g_r2[B_TOT * 8];

// ---------------- helpers ----------------
__device__ __forceinline__ uint32_t smem_u32(const void* p) {
    uint32_t a;
    asm("{ .reg .u64 t; cvta.to.shared.u64 t, %1; cvt.u32.u64 %0, t; }" : "=r"(a) : "l"(p));
    return a;
}
__device__ __forceinline__ void cp16(uint32_t dst, const void* src) {
    asm volatile("cp.async.cg.shared.global [%0], [%1], 16;" :: "r"(dst), "l"(src) : "memory");
}
#define CP_COMMIT() asm volatile("cp.async.commit_group;" ::: "memory")
__device__ __forceinline__ void cp_wait_n(int n) {
    if (n <= 0)      asm volatile("cp.async.wait_group 0;" ::: "memory");
    else if (n == 1) asm volatile("cp.async.wait_group 1;" ::: "memory");
    else if (n == 2) asm volatile("cp.async.wait_group 2;" ::: "memory");
    // n >= 3: nothing to wait for
}
__device__ __forceinline__ void ldm4t(uint32_t& r0, uint32_t& r1, uint32_t& r2, uint32_t& r3,
                                      uint32_t addr) {
    asm volatile("ldmatrix.sync.aligned.m8n8.x4.trans.shared.b16 {%0,%1,%2,%3}, [%4];"
                 : "=r"(r0), "=r"(r1), "=r"(r2), "=r"(r3) : "r"(addr));
}
__device__ __forceinline__ void mma16816(float c[4], uint32_t a0, uint32_t a1,
                                         uint32_t a2, uint32_t a3,
                                         uint32_t b0, uint32_t b1) {
    asm volatile(
        "mma.sync.aligned.m16n8k16.row.col.f32.f16.f16.f32 "
        "{%0,%1,%2,%3}, {%4,%5,%6,%7}, {%8,%9}, {%0,%1,%2,%3};"
        : "+f"(c[0]), "+f"(c[1]), "+f"(c[2]), "+f"(c[3])
        : "r"(a0), "r"(a1), "r"(a2), "r"(a3), "r"(b0), "r"(b1));
}

// =====================================================================
// prep: f16 copies (k-row-major everywhere)
// =====================================================================
__global__ void prep_kernel(const float* __restrict__ W1, const float* __restrict__ W2,
                            const float* __restrict__ W3) {
    int idx = blockIdx.x * 256 + threadIdx.x;
    if (idx < 65536) g_W2f[idx] = __float2half_rn(W2[idx]);
    else if (idx < 131072) g_W1f[idx - 65536] = __float2half_rn(W1[idx - 65536]);
    else {
        int l = idx - 131072;
        int i = l >> 6, o = l & 63;
        g_W3T[l] = __float2half_rn(W3[o * 256 + i]);
    }
}

// =====================================================================
// forward MLP (fp32 exact) + ReLU bitmasks, 16 samples / block
// =====================================================================
__global__ __launch_bounds__(256) void fwd_kernel(
    const float* __restrict__ X,
    const float* __restrict__ W1, const float* __restrict__ B1,
    const float* __restrict__ W2, const float* __restrict__ B2,
    const float* __restrict__ W3, const float* __restrict__ B3)
{
    __shared__ float bufA[16][256];
    __shared__ float bufB[16][256];
    const int t = threadIdx.x, lane = t & 31, wid = t >> 5;
    const int s0 = blockIdx.x * 16;

    {
        const float4* src = (const float4*)(X + (size_t)s0 * 256);
        float4* dst = (float4*)&bufA[0][0];
        for (int i = t; i < 16 * 64; i += 256) dst[i] = __ldg(src + i);
    }
    __syncthreads();

    float acc[16];
    {   // layer 1
        #pragma unroll
        for (int s = 0; s < 16; ++s) acc[s] = 0.f;
        const float4* wr = (const float4*)(W1 + t * 256);
        for (int j = 0; j < 64; ++j) {
            float4 w = __ldg(wr + j);
            #pragma unroll
            for (int s = 0; s < 16; ++s) {
                float4 xv = ((const float4*)bufA[s])[j];
                acc[s] = fmaf(w.x, xv.x, acc[s]); acc[s] = fmaf(w.y, xv.y, acc[s]);
                acc[s] = fmaf(w.z, xv.z, acc[s]); acc[s] = fmaf(w.w, xv.w, acc[s]);
            }
        }
        const float b = __ldg(B1 + t);
        #pragma unroll
        for (int s = 0; s < 16; ++s) {
            float z = acc[s] + b;
            unsigned m = __ballot_sync(0xffffffffu, z > 0.f);
            if (lane == 0) g_r1[(size_t)(s0 + s) * 8 + wid] = m;
            bufB[s][t] = z > 0.f ? z : 0.f;
        }
    }
    __syncthreads();
    {   // layer 2
        #pragma unroll
        for (int s = 0; s < 16; ++s) acc[s] = 0.f;
        const float4* wr = (const float4*)(W2 + t * 256);
        for (int j = 0; j < 64; ++j) {
            float4 w = __ldg(wr + j);
            #pragma unroll
            for (int s = 0; s < 16; ++s) {
                float4 xv = ((const float4*)bufB[s])[j];
                acc[s] = fmaf(w.x, xv.x, acc[s]); acc[s] = fmaf(w.y, xv.y, acc[s]);
                acc[s] = fmaf(w.z, xv.z, acc[s]); acc[s] = fmaf(w.w, xv.w, acc[s]);
            }
        }
        const float b = __ldg(B2 + t);
        #pragma unroll
        for (int s = 0; s < 16; ++s) {
            float z = acc[s] + b;
            unsigned m = __ballot_sync(0xffffffffu, z > 0.f);
            if (lane == 0) g_r2[(size_t)(s0 + s) * 8 + wid] = m;
            bufA[s][t] = z > 0.f ? z : 0.f;
        }
    }
    __syncthreads();
    {   // layer 3
        const int o = t & 63, sg = t >> 6;
        float a4[4] = {0.f, 0.f, 0.f, 0.f};
        const float4* wr = (const float4*)(W3 + o * 256);
        for (int j = 0; j < 64; ++j) {
            float4 w = __ldg(wr + j);
            #pragma unroll
            for (int q = 0; q < 4; ++q) {
                float4 hv = ((const float4*)bufA[sg * 4 + q])[j];
                a4[q] = fmaf(w.x, hv.x, a4[q]); a4[q] = fmaf(w.y, hv.y, a4[q]);
                a4[q] = fmaf(w.z, hv.z, a4[q]); a4[q] = fmaf(w.w, hv.w, a4[q]);
            }
        }
        const float b = __ldg(B3 + o);
        #pragma unroll
        for (int q = 0; q < 4; ++q)
            g_f[(size_t)(s0 + sg * 4 + q) * 64 + o] = a4[q] + b;
    }
}

// =====================================================================
// jac kernel: 1 sample/CTA, unified cp.async pipeline over both GEMMs.
// Max 3 groups in flight (4-slot ring; slot (c+3)&3 never collides with
// live slots c..c+2). A/U buffer [256 x 144B], ring 4 x (16 x 528B).
// =====================================================================
#define A_PITCH  144
#define B_PITCH  528
#define RING_SLOT 8448          // 16 * 528
#define SM_RING  36864u
#define SM_MSC   70656u
#define SMEMJ    72448

__global__ __launch_bounds__(256, 2) void jac_kernel(const float* __restrict__ Kp,
                                                     float* __restrict__ out) {
    extern __shared__ char smem[];
    const uint32_t sb = smem_u32(smem);
    const int tid = threadIdx.x, lane = tid & 31, wid = tid >> 5;
    const int g = lane >> 2, tig = lane & 3;
    const int wm = wid & 1, wn = wid >> 1;      // 2 x 4 warp grid, 32 x 64 tiles
    const int s = blockIdx.x;

    unsigned* m2s = (unsigned*)(smem + SM_MSC);            // 8
    unsigned* m1s = (unsigned*)(smem + SM_MSC + 32);       // 8
    unsigned* p2s = (unsigned*)(smem + SM_MSC + 64);       // 9 (+pad)
    unsigned* p1s = (unsigned*)(smem + SM_MSC + 104);      // 9 (+pad)
    unsigned short* idx2 = (unsigned short*)(smem + SM_MSC + 144);   // 256
    unsigned short* idx1 = (unsigned short*)(smem + SM_MSC + 656);   // 256
    unsigned short* pos1 = (unsigned short*)(smem + SM_MSC + 1168);  // 256
    float* red = (float*)(smem + SM_MSC + 1680);           // 8

    // ---- masks ----
    if (tid < 8)       m2s[tid]     = g_r2[(size_t)s * 8 + tid];
    else if (tid < 16) m1s[tid - 8] = g_r1[(size_t)s * 8 + (tid - 8)];
    __syncthreads();
    if (tid == 0)  { unsigned p = 0; for (int w = 0; w < 8; ++w) { p2s[w] = p; p += __popc(m2s[w]); } p2s[8] = p; }
    if (tid == 32) { unsigned p = 0; for (int w = 0; w < 8; ++w) { p1s[w] = p; p += __popc(m1s[w]); } p1s[8] = p; }
    __syncthreads();
    const int n2 = p2s[8], n1 = p1s[8];
    int nch2 = (n2 + 15) >> 4; if (nch2 < 1) nch2 = 1;
    int nch1 = (n1 + 15) >> 4; if (nch1 < 1) nch1 = 1;
    {
        const int j = tid, w = j >> 5, bi = j & 31;
        const unsigned below = (bi == 0) ? 0u : ((1u << bi) - 1u);
        if ((m2s[w] >> bi) & 1u)
            idx2[p2s[w] + __popc(m2s[w] & below)] = (unsigned short)j;
        if ((m1s[w] >> bi) & 1u) {
            unsigned p = p1s[w] + __popc(m1s[w] & below);
            idx1[p] = (unsigned short)j;
            pos1[j] = (unsigned short)p;
        }
        if (tid >= n2) idx2[tid] = 0;
        if (tid >= n1) idx1[tid] = 0;
    }
    __syncthreads();

    const int total = nch2 + nch1;

    // ---- gather helper: chunk seq (16 rows x 512B) into ring slot seq&3 ----
    auto gatherB = [&](int seq) {
        const __half* W; const unsigned short* idx; int c;
        if (seq < nch2) { W = g_W2f; idx = idx2; c = seq; }
        else            { W = g_W1f; idx = idx1; c = seq - nch2; }
        const uint32_t base = sb + SM_RING + (uint32_t)(seq & 3) * RING_SLOT;
        #pragma unroll
        for (int p = 0; p < 2; ++p) {
            const int i = tid + p * 256;
            const int row = i >> 5, seg = i & 31;
            cp16(base + (uint32_t)row * B_PITCH + (uint32_t)seg * 16u,
                 (const char*)W + (size_t)idx[c * 16 + row] * 512 + (size_t)seg * 16);
        }
    };

    // ---- group 0: A gather + chunk 0; prefill to at most 3 in flight ----
    for (int i = tid; i < n2 * 8; i += 256)
        cp16(sb + (uint32_t)(i >> 3) * A_PITCH + (uint32_t)(i & 7) * 16u,
             (const char*)g_W3T + (size_t)idx2[i >> 3] * 128 + (size_t)(i & 7) * 16);
    gatherB(0);
    CP_COMMIT();
    int issued = 1;
    while (issued < total && issued < 3) { gatherB(issued); CP_COMMIT(); ++issued; }

    // zero A pad rows [n2, nch2*16)
    for (int i = tid; i < (nch2 * 16 - n2) * 8; i += 256) {
        const int r = n2 + (i >> 3), seg = i & 7;
        *(uint4*)(smem + r * A_PITCH + seg * 16) = make_uint4(0, 0, 0, 0);
    }

    float acc[2][8][4];
    #pragma unroll
    for (int mt = 0; mt < 2; ++mt)
        #pragma unroll
        for (int nt = 0; nt < 8; ++nt)
            #pragma unroll
            for (int q = 0; q < 4; ++q) acc[mt][nt][q] = 0.f;

    const int rlA = (lane & 7) + ((lane >> 4) & 1) * 8;
    const int rlB = (lane & 7) + ((lane >> 3) & 1) * 8;
    const uint32_t aCol = ((lane >> 3) & 1) * 16 + (uint32_t)wm * 64u;
    const uint32_t bCol = ((lane >> 4) & 1) * 16 + (uint32_t)wn * 128u;

    for (int c = 0; c < total; ++c) {
        cp_wait_n(issued - c - 1);
        __syncthreads();

        if (c == nch2) {
            // scatter masked U (compact rows, pitch 144) and reset acc
            #pragma unroll
            for (int mt = 0; mt < 2; ++mt)
                #pragma unroll
                for (int nt = 0; nt < 8; ++nt)
                    #pragma unroll
                    for (int q = 0; q < 4; ++q) {
                        const int m = wm * 32 + mt * 16 + g + (q >> 1) * 8;
                        const int j = wn * 64 + nt * 8 + 2 * tig + (q & 1);
                        if ((m1s[j >> 5] >> (j & 31)) & 1u)
                            *(__half*)(smem + (uint32_t)pos1[j] * A_PITCH + (uint32_t)m * 2u) =
                                __float2half_rn(acc[mt][nt][q]);
                        acc[mt][nt][q] = 0.f;
                    }
            // zero U pad rows [n1, nch1*16)
            for (int i = tid; i < (nch1 * 16 - n1) * 8; i += 256) {
                const int r = n1 + (i >> 3), seg = i & 7;
                *(uint4*)(smem + r * A_PITCH + seg * 16) = make_uint4(0, 0, 0, 0);
            }
            __syncthreads();
        }

        // issue next gather (slot (c+3)&3 — distinct from live slots c..c+2)
        if (issued < total && issued <= c + 3) { gatherB(issued); CP_COMMIT(); ++issued; }

        // ---- mma on chunk c ----
        const int arow = (c < nch2 ? c : c - nch2) * 16;
        const uint32_t aadr = sb + (uint32_t)(arow + rlA) * A_PITCH + aCol;
        const uint32_t badr = sb + SM_RING + (uint32_t)(c & 3) * RING_SLOT
                              + (uint32_t)rlB * B_PITCH + bCol;
        uint32_t a[2][4], b[4][4];
        #pragma unroll
        for (int mt = 0; mt < 2; ++mt)
            ldm4t(a[mt][0], a[mt][1], a[mt][2], a[mt][3], aadr + (uint32_t)mt * 32u);
        #pragma unroll
        for (int ng = 0; ng < 4; ++ng)
            ldm4t(b[ng][0], b[ng][1], b[ng][2], b[ng][3], badr + (uint32_t)ng * 32u);
        #pragma unroll
        for (int mt = 0; mt < 2; ++mt)
            #pragma unroll
            for (int nt = 0; nt < 8; ++nt)
                mma16816(acc[mt][nt], a[mt][0], a[mt][1], a[mt][2], a[mt][3],
                         b[nt >> 1][(nt & 1) * 2], b[nt >> 1][(nt & 1) * 2 + 1]);
    }

    // ---- ||J||^2 + epilogue ----
    float ss = 0.f;
    #pragma unroll
    for (int mt = 0; mt < 2; ++mt)
        #pragma unroll
        for (int nt = 0; nt < 8; ++nt)
            #pragma unroll
            for (int q = 0; q < 4; ++q)
                ss = fmaf(acc[mt][nt][q], acc[mt][nt][q], ss);
    #pragma unroll
    for (int off = 16; off; off >>= 1)
        ss += __shfl_xor_sync(0xffffffffu, ss, off);
    if (lane == 0) red[wid] = ss;
    __syncthreads();

    if (tid < 64) {
        const float jn2 = red[0] + red[1] + red[2] + red[3] +
                          red[4] + red[5] + red[6] + red[7];
        const float fv = g_f[(size_t)s * 64 + tid];
        const float kk = __ldg(Kp);
        const float sp = (kk > 20.f) ? kk : log1pf(expf(kk));
        out[(size_t)s * 64 + tid] = tanhf(sp * fv / (sqrtf(jn2) + 1e-4f));
    }
}

// =====================================================================
extern "C" void kernel_launch(void* const* d_in, const int* in_sizes, int n_in,
                              void* d_out, int out_size)
{
    const float* X  = (const float*)d_in[0];
    const float* W1 = (const float*)d_in[1];
    const float* B1 = (const float*)d_in[2];
    const float* W2 = (const float*)d_in[3];
    const float* B2 = (const float*)d_in[4];
    const float* W3 = (const float*)d_in[5];
    const float* B3 = (const float*)d_in[6];
    const float* Kp = (const float*)d_in[7];
    float* out = (float*)d_out;

    cudaFuncSetAttribute(jac_kernel, cudaFuncAttributeMaxDynamicSharedMemorySize, SMEMJ);

    prep_kernel<<<576, 256>>>(W1, W2, W3);
    fwd_kernel<<<B_TOT / 16, 256>>>(X, W1, B1, W2, B2, W3, B3);
    jac_kernel<<<B_TOT, 256, SMEMJ>>>(Kp, out);
}

// round 17
// speedup vs baseline: 1.3673x; 1.0291x over previous
#include <cuda_runtime.h>
#include <cuda_fp16.h>
#include <cstdint>

#define B_TOT 8192

// ---------------- device scratch ----------------
__device__ __align__(16) __half g_W2f[256 * 256];  // W2 f16 (B of GEMM1, k-row-major)
__device__ __align__(16) __half g_W1f[256 * 256];  // W1 f16 (B of GEMM2)
__device__ __align__(16) __half g_W3T[256 * 64];   // W3^T f16 (A of GEMM1: [i][o])
__device__ __align__(16) float  g_f[B_TOT * 64];
__device__ unsigned g_r1[B_TOT * 8];
__device__ unsigned g_r2[B_TOT * 8];

// ---------------- helpers ----------------
__device__ __forceinline__ uint32_t smem_u32(const void* p) {
    uint32_t a;
    asm("{ .reg .u64 t; cvta.to.shared.u64 t, %1; cvt.u32.u64 %0, t; }" : "=r"(a) : "l"(p));
    return a;
}
__device__ __forceinline__ void cp16(uint32_t dst, const void* src) {
    asm volatile("cp.async.cg.shared.global [%0], [%1], 16;" :: "r"(dst), "l"(src) : "memory");
}
#define CP_COMMIT() asm volatile("cp.async.commit_group;" ::: "memory")
__device__ __forceinline__ void cp_wait_n(int n) {
    if (n <= 0)      asm volatile("cp.async.wait_group 0;" ::: "memory");
    else if (n == 1) asm volatile("cp.async.wait_group 1;" ::: "memory");
}
__device__ __forceinline__ void ldm4t(uint32_t& r0, uint32_t& r1, uint32_t& r2, uint32_t& r3,
                                      uint32_t addr) {
    asm volatile("ldmatrix.sync.aligned.m8n8.x4.trans.shared.b16 {%0,%1,%2,%3}, [%4];"
                 : "=r"(r0), "=r"(r1), "=r"(r2), "=r"(r3) : "r"(addr));
}
__device__ __forceinline__ void mma16816(float c[4], uint32_t a0, uint32_t a1,
                                         uint32_t a2, uint32_t a3,
                                         uint32_t b0, uint32_t b1) {
    asm volatile(
        "mma.sync.aligned.m16n8k16.row.col.f32.f16.f16.f32 "
        "{%0,%1,%2,%3}, {%4,%5,%6,%7}, {%8,%9}, {%0,%1,%2,%3};"
        : "+f"(c[0]), "+f"(c[1]), "+f"(c[2]), "+f"(c[3])
        : "r"(a0), "r"(a1), "r"(a2), "r"(a3), "r"(b0), "r"(b1));
}
// packed f32x2 FMA (sm_100+; validated on this toolchain in R1)
__device__ __forceinline__ void ffma2(unsigned long long& d, unsigned long long a,
                                      unsigned long long b) {
    asm("fma.rn.f32x2 %0, %1, %2, %0;" : "+l"(d) : "l"(a), "l"(b));
}
__device__ __forceinline__ float sum2(unsigned long long v) {
    float lo, hi;
    asm("mov.b64 {%0, %1}, %2;" : "=f"(lo), "=f"(hi) : "l"(v));
    return lo + hi;
}

// =====================================================================
// prep: f16 copies (k-row-major everywhere)
// =====================================================================
__global__ void prep_kernel(const float* __restrict__ W1, const float* __restrict__ W2,
                            const float* __restrict__ W3) {
    int idx = blockIdx.x * 256 + threadIdx.x;
    if (idx < 65536) g_W2f[idx] = __float2half_rn(W2[idx]);
    else if (idx < 131072) g_W1f[idx - 65536] = __float2half_rn(W1[idx - 65536]);
    else {
        int l = idx - 131072;
        int i = l >> 6, o = l & 63;
        g_W3T[l] = __float2half_rn(W3[o * 256 + i]);
    }
}

// =====================================================================
// forward MLP (fp32, packed f32x2 FMA) + ReLU bitmasks, 16 samples/block
// =====================================================================
__global__ __launch_bounds__(256) void fwd_kernel(
    const float* __restrict__ X,
    const float* __restrict__ W1, const float* __restrict__ B1,
    const float* __restrict__ W2, const float* __restrict__ B2,
    const float* __restrict__ W3, const float* __restrict__ B3)
{
    __shared__ float bufA[16][256];
    __shared__ float bufB[16][256];
    const int t = threadIdx.x, lane = t & 31, wid = t >> 5;
    const int s0 = blockIdx.x * 16;

    {
        const float4* src = (const float4*)(X + (size_t)s0 * 256);
        float4* dst = (float4*)&bufA[0][0];
        for (int i = t; i < 16 * 64; i += 256) dst[i] = __ldg(src + i);
    }
    __syncthreads();

    unsigned long long aL[16], aH[16];
    {   // layer 1
        #pragma unroll
        for (int s = 0; s < 16; ++s) { aL[s] = 0ull; aH[s] = 0ull; }
        const ulonglong2* wr = (const ulonglong2*)(W1 + t * 256);
        for (int j = 0; j < 64; ++j) {
            ulonglong2 w = wr[j];
            #pragma unroll
            for (int s = 0; s < 16; ++s) {
                ulonglong2 xv = ((const ulonglong2*)bufA[s])[j];
                ffma2(aL[s], w.x, xv.x);
                ffma2(aH[s], w.y, xv.y);
            }
        }
        const float b = __ldg(B1 + t);
        #pragma unroll
        for (int s = 0; s < 16; ++s) {
            float z = sum2(aL[s]) + sum2(aH[s]) + b;
            unsigned m = __ballot_sync(0xffffffffu, z > 0.f);
            if (lane == 0) g_r1[(size_t)(s0 + s) * 8 + wid] = m;
            bufB[s][t] = z > 0.f ? z : 0.f;
        }
    }
    __syncthreads();
    {   // layer 2
        #pragma unroll
        for (int s = 0; s < 16; ++s) { aL[s] = 0ull; aH[s] = 0ull; }
        const ulonglong2* wr = (const ulonglong2*)(W2 + t * 256);
        for (int j = 0; j < 64; ++j) {
            ulonglong2 w = wr[j];
            #pragma unroll
            for (int s = 0; s < 16; ++s) {
                ulonglong2 xv = ((const ulonglong2*)bufB[s])[j];
                ffma2(aL[s], w.x, xv.x);
                ffma2(aH[s], w.y, xv.y);
            }
        }
        const float b = __ldg(B2 + t);
        #pragma unroll
        for (int s = 0; s < 16; ++s) {
            float z = sum2(aL[s]) + sum2(aH[s]) + b;
            unsigned m = __ballot_sync(0xffffffffu, z > 0.f);
            if (lane == 0) g_r2[(size_t)(s0 + s) * 8 + wid] = m;
            bufA[s][t] = z > 0.f ? z : 0.f;
        }
    }
    __syncthreads();
    {   // layer 3: thread t -> o = t&63, 4 samples
        const int o = t & 63, sg = t >> 6;
        unsigned long long cL[4] = {0ull, 0ull, 0ull, 0ull};
        unsigned long long cH[4] = {0ull, 0ull, 0ull, 0ull};
        const ulonglong2* wr = (const ulonglong2*)(W3 + o * 256);
        for (int j = 0; j < 64; ++j) {
            ulonglong2 w = wr[j];
            #pragma unroll
            for (int q = 0; q < 4; ++q) {
                ulonglong2 hv = ((const ulonglong2*)bufA[sg * 4 + q])[j];
                ffma2(cL[q], w.x, hv.x);
                ffma2(cH[q], w.y, hv.y);
            }
        }
        const float b = __ldg(B3 + o);
        #pragma unroll
        for (int q = 0; q < 4; ++q)
            g_f[(size_t)(s0 + sg * 4 + q) * 64 + o] = sum2(cL[q]) + sum2(cH[q]) + b;
    }
}

// =====================================================================
// jac kernel: 1 sample/CTA, unified cp.async pipeline over both GEMMs.
// 32-row chunks, 3-slot ring (lookahead 2). A/U buffer [256 x 144B].
// =====================================================================
#define A_PITCH   144
#define B_PITCH   528
#define RING_SLOT 16896         // 32 * 528
#define SM_RING   36864u
#define SM_MSC    87552u
#define SMEMJ     89344

__global__ __launch_bounds__(256, 2) void jac_kernel(const float* __restrict__ Kp,
                                                     float* __restrict__ out) {
    extern __shared__ char smem[];
    const uint32_t sb = smem_u32(smem);
    const int tid = threadIdx.x, lane = tid & 31, wid = tid >> 5;
    const int g = lane >> 2, tig = lane & 3;
    const int wm = wid & 1, wn = wid >> 1;      // 2 x 4 warp grid, 32 x 64 tiles
    const int s = blockIdx.x;

    unsigned* m2s = (unsigned*)(smem + SM_MSC);            // 8
    unsigned* m1s = (unsigned*)(smem + SM_MSC + 32);       // 8
    unsigned* p2s = (unsigned*)(smem + SM_MSC + 64);       // 9 (+pad)
    unsigned* p1s = (unsigned*)(smem + SM_MSC + 104);      // 9 (+pad)
    unsigned short* idx2 = (unsigned short*)(smem + SM_MSC + 144);   // 256
    unsigned short* idx1 = (unsigned short*)(smem + SM_MSC + 656);   // 256
    unsigned short* pos1 = (unsigned short*)(smem + SM_MSC + 1168);  // 256
    float* red = (float*)(smem + SM_MSC + 1680);           // 8

    // ---- masks ----
    if (tid < 8)       m2s[tid]     = g_r2[(size_t)s * 8 + tid];
    else if (tid < 16) m1s[tid - 8] = g_r1[(size_t)s * 8 + (tid - 8)];
    __syncthreads();
    if (tid == 0)  { unsigned p = 0; for (int w = 0; w < 8; ++w) { p2s[w] = p; p += __popc(m2s[w]); } p2s[8] = p; }
    if (tid == 32) { unsigned p = 0; for (int w = 0; w < 8; ++w) { p1s[w] = p; p += __popc(m1s[w]); } p1s[8] = p; }
    __syncthreads();
    const int n2 = p2s[8], n1 = p1s[8];
    int nch2 = (n2 + 31) >> 5; if (nch2 < 1) nch2 = 1;
    int nch1 = (n1 + 31) >> 5; if (nch1 < 1) nch1 = 1;
    {
        const int j = tid, w = j >> 5, bi = j & 31;
        const unsigned below = (bi == 0) ? 0u : ((1u << bi) - 1u);
        if ((m2s[w] >> bi) & 1u)
            idx2[p2s[w] + __popc(m2s[w] & below)] = (unsigned short)j;
        if ((m1s[w] >> bi) & 1u) {
            unsigned p = p1s[w] + __popc(m1s[w] & below);
            idx1[p] = (unsigned short)j;
            pos1[j] = (unsigned short)p;
        }
        if (tid >= n2) idx2[tid] = 0;
        if (tid >= n1) idx1[tid] = 0;
    }
    __syncthreads();

    const int total = nch2 + nch1;

    // ---- gather: chunk seq (32 rows x 512B) into ring slot seq%3 ----
    auto gatherB = [&](int seq) {
        const __half* W; const unsigned short* idx; int c;
        if (seq < nch2) { W = g_W2f; idx = idx2; c = seq; }
        else            { W = g_W1f; idx = idx1; c = seq - nch2; }
        const uint32_t base = sb + SM_RING + (uint32_t)(seq % 3) * RING_SLOT;
        #pragma unroll
        for (int p = 0; p < 4; ++p) {
            const int i = tid + p * 256;
            const int row = i >> 5, seg = i & 31;
            cp16(base + (uint32_t)row * B_PITCH + (uint32_t)seg * 16u,
                 (const char*)W + (size_t)idx[c * 32 + row] * 512 + (size_t)seg * 16);
        }
    };

    // ---- group 0: A gather + chunk 0; prefill to at most 2 in flight ----
    for (int i = tid; i < n2 * 8; i += 256)
        cp16(sb + (uint32_t)(i >> 3) * A_PITCH + (uint32_t)(i & 7) * 16u,
             (const char*)g_W3T + (size_t)idx2[i >> 3] * 128 + (size_t)(i & 7) * 16);
    gatherB(0);
    CP_COMMIT();
    int issued = 1;
    if (issued < total) { gatherB(issued); CP_COMMIT(); ++issued; }

    // zero A pad rows [n2, nch2*32)
    for (int i = tid; i < (nch2 * 32 - n2) * 8; i += 256) {
        const int r = n2 + (i >> 3), seg = i & 7;
        *(uint4*)(smem + r * A_PITCH + seg * 16) = make_uint4(0, 0, 0, 0);
    }

    float acc[2][8][4];
    #pragma unroll
    for (int mt = 0; mt < 2; ++mt)
        #pragma unroll
        for (int nt = 0; nt < 8; ++nt)
            #pragma unroll
            for (int q = 0; q < 4; ++q) acc[mt][nt][q] = 0.f;

    const int rlA = (lane & 7) + ((lane >> 4) & 1) * 8;
    const int rlB = (lane & 7) + ((lane >> 3) & 1) * 8;
    const uint32_t aCol = ((lane >> 3) & 1) * 16 + (uint32_t)wm * 64u;
    const uint32_t bCol = ((lane >> 4) & 1) * 16 + (uint32_t)wn * 128u;

    for (int c = 0; c < total; ++c) {
        cp_wait_n(issued - c - 1);
        __syncthreads();

        if (c == nch2) {
            // scatter masked U (compact rows, pitch 144) and reset acc
            #pragma unroll
            for (int mt = 0; mt < 2; ++mt)
                #pragma unroll
                for (int nt = 0; nt < 8; ++nt)
                    #pragma unroll
                    for (int q = 0; q < 4; ++q) {
                        const int m = wm * 32 + mt * 16 + g + (q >> 1) * 8;
                        const int j = wn * 64 + nt * 8 + 2 * tig + (q & 1);
                        if ((m1s[j >> 5] >> (j & 31)) & 1u)
                            *(__half*)(smem + (uint32_t)pos1[j] * A_PITCH + (uint32_t)m * 2u) =
                                __float2half_rn(acc[mt][nt][q]);
                        acc[mt][nt][q] = 0.f;
                    }
            // zero U pad rows [n1, nch1*32)
            for (int i = tid; i < (nch1 * 32 - n1) * 8; i += 256) {
                const int r = n1 + (i >> 3), seg = i & 7;
                *(uint4*)(smem + r * A_PITCH + seg * 16) = make_uint4(0, 0, 0, 0);
            }
            __syncthreads();
        }

        // issue next gather into slot (c+2)%3 (distinct from live c, c+1)
        if (issued < total && issued <= c + 2) { gatherB(issued); CP_COMMIT(); ++issued; }

        // ---- mma on chunk c (2 k16 sub-steps) ----
        const int arow0 = (c < nch2 ? c : c - nch2) * 32;
        const uint32_t slotb = sb + SM_RING + (uint32_t)(c % 3) * RING_SLOT;
        #pragma unroll
        for (int ks = 0; ks < 2; ++ks) {
            const uint32_t aadr = sb + (uint32_t)(arow0 + ks * 16 + rlA) * A_PITCH + aCol;
            const uint32_t badr = slotb + (uint32_t)(ks * 16 + rlB) * B_PITCH + bCol;
            uint32_t a[2][4], b[4][4];
            #pragma unroll
            for (int mt = 0; mt < 2; ++mt)
                ldm4t(a[mt][0], a[mt][1], a[mt][2], a[mt][3], aadr + (uint32_t)mt * 32u);
            #pragma unroll
            for (int ng = 0; ng < 4; ++ng)
                ldm4t(b[ng][0], b[ng][1], b[ng][2], b[ng][3], badr + (uint32_t)ng * 32u);
            #pragma unroll
            for (int mt = 0; mt < 2; ++mt)
                #pragma unroll
                for (int nt = 0; nt < 8; ++nt)
                    mma16816(acc[mt][nt], a[mt][0], a[mt][1], a[mt][2], a[mt][3],
                             b[nt >> 1][(nt & 1) * 2], b[nt >> 1][(nt & 1) * 2 + 1]);
        }
    }

    // ---- ||J||^2 + epilogue ----
    float ss = 0.f;
    #pragma unroll
    for (int mt = 0; mt < 2; ++mt)
        #pragma unroll
        for (int nt = 0; nt < 8; ++nt)
            #pragma unroll
            for (int q = 0; q < 4; ++q)
                ss = fmaf(acc[mt][nt][q], acc[mt][nt][q], ss);
    #pragma unroll
    for (int off = 16; off; off >>= 1)
        ss += __shfl_xor_sync(0xffffffffu, ss, off);
    if (lane == 0) red[wid] = ss;
    __syncthreads();

    if (tid < 64) {
        const float jn2 = red[0] + red[1] + red[2] + red[3] +
                          red[4] + red[5] + red[6] + red[7];
        const float fv = g_f[(size_t)s * 64 + tid];
        const float kk = __ldg(Kp);
        const float sp = (kk > 20.f) ? kk : log1pf(expf(kk));
        out[(size_t)s * 64 + tid] = tanhf(sp * fv / (sqrtf(jn2) + 1e-4f));
    }
}

// =====================================================================
extern "C" void kernel_launch(void* const* d_in, const int* in_sizes, int n_in,
                              void* d_out, int out_size)
{
    const float* X  = (const float*)d_in[0];
    const float* W1 = (const float*)d_in[1];
    const float* B1 = (const float*)d_in[2];
    const float* W2 = (const float*)d_in[3];
    const float* B2 = (const float*)d_in[4];
    const float* W3 = (const float*)d_in[5];
    const float* B3 = (const float*)d_in[6];
    const float* Kp = (const float*)d_in[7];
    float* out = (float*)d_out;

    cudaFuncSetAttribute(jac_kernel, cudaFuncAttributeMaxDynamicSharedMemorySize, SMEMJ);

    prep_kernel<<<576, 256>>>(W1, W2, W3);
    fwd_kernel<<<B_TOT / 16, 256>>>(X, W1, B1, W2, B2, W3, B3);
    jac_kernel<<<B_TOT, 256, SMEMJ>>>(Kp, out);
}